// round 3
// baseline (speedup 1.0000x reference)
#include <cuda_runtime.h>
#include <stdint.h>

// ---------------------------------------------------------------------------
// MultiHeadAttention: out = LN(ctx@W_fc + X@W_fc0), attn materialized.
// B=8, S=2048, D=128, H=4, dk=dv=32.
// Output buffer layout: [out (8*2048*128)] then [attn (8*4*2048*2048)].
// ---------------------------------------------------------------------------

namespace {
constexpr int BATCH = 8;
constexpr int SEQ   = 2048;
constexpr int DM    = 128;
constexpr int NH    = 4;
constexpr int DKC   = 32;
constexpr int NR    = BATCH * SEQ;                 // 16384 rows
constexpr size_t OUT_ELEMS = (size_t)NR * DM;      // 2,097,152
constexpr int TQ = 128;                            // q-tile per block
constexpr int TK = 64;                             // k-chunk
// dynamic smem layout for attn kernel (floats)
constexpr int SQT_OFF = 0;                 // sQt[32][132]
constexpr int SKT_OFF = 32 * 132;          // sKt[32][68]
constexpr int SVT_OFF = SKT_OFF + 32 * 68; // sVt[32][68]
constexpr int SS_OFF  = SVT_OFF + 32 * 68; // sS [128][68]
constexpr int SMEM_FLOATS = SS_OFF + 128 * 68;
constexpr size_t SMEM_BYTES = (size_t)SMEM_FLOATS * 4;  // 69,120 B
}

// Scratch (device globals: allocation-free rule)
__device__ float g_R  [NR * DM];
__device__ float g_Qp [NR * DM];
__device__ float g_Kp [NR * DM];
__device__ float g_Vp [NR * DM];
__device__ float g_ctx[NR * DM];
__device__ float g_rinv[BATCH * NH * SEQ];
__device__ int   g_mask_mode;   // 0=uint8, 1=int32, 2=float32

// ---------------------------------------------------------------------------
// fast exp via FMA pipe: exp(s*scale) = 2^(s*C), C = scale*log2(e).
// Round-to-int trick + degree-6 Taylor of 2^r on r in [-0.5, 0.5].
// Max rel error ~1.2e-7. Avoids MUFU (rt 8 cyc/SMSP -> chip bottleneck).
// ---------------------------------------------------------------------------
__device__ __forceinline__ float exp2_poly(float y)
{
    float t   = __fadd_rn(y, 12582912.0f);         // 1.5*2^23: round y to int
    float n_f = __fsub_rn(t, 12582912.0f);
    float r   = __fsub_rn(y, n_f);                 // r in [-0.5, 0.5]
    int   n   = __float_as_int(t) - 0x4B400000;    // integer part (signed)
    float p   = 1.540353039e-4f;                   // ln2^6/720
    p = __fmaf_rn(p, r, 1.333355815e-3f);          // ln2^5/120
    p = __fmaf_rn(p, r, 9.618129107e-3f);          // ln2^4/24
    p = __fmaf_rn(p, r, 5.550410866e-2f);          // ln2^3/6
    p = __fmaf_rn(p, r, 2.402265070e-1f);          // ln2^2/2
    p = __fmaf_rn(p, r, 6.931471806e-1f);          // ln2
    p = __fmaf_rn(p, r, 1.0f);
    return __int_as_float(__float_as_int(p) + (n << 23));
}

// ---------------------------------------------------------------------------
// K0: detect mask dtype from byte patterns in the first 4096 bytes.
// ---------------------------------------------------------------------------
__global__ void detect_mask(const unsigned char* __restrict__ m)
{
    __shared__ int s_gt1, s_off;
    if (threadIdx.x == 0) { s_gt1 = 0; s_off = 0; }
    __syncthreads();
    int gt1 = 0, off = 0;
    for (int i = threadIdx.x; i < 4096; i += 256) {
        unsigned char v = m[i];
        if (v > 1) gt1 = 1;
        else if (v == 1 && (i & 3) != 0) off = 1;
    }
    if (gt1) atomicOr(&s_gt1, 1);
    if (off) atomicOr(&s_off, 1);
    __syncthreads();
    if (threadIdx.x == 0)
        g_mask_mode = s_gt1 ? 2 : (s_off ? 0 : 1);
}

__device__ __forceinline__ uint4 load_mask4(const unsigned char* __restrict__ mask,
                                            size_t idx, int mode)
{
    if (mode == 0) {
        uchar4 m = *(const uchar4*)(mask + idx);
        return make_uint4(m.x, m.y, m.z, m.w);
    } else if (mode == 1) {
        int4 m = *(const int4*)((const int*)mask + idx);
        return make_uint4((unsigned)m.x, (unsigned)m.y, (unsigned)m.z, (unsigned)m.w);
    } else {
        float4 m = *(const float4*)((const float*)mask + idx);
        return make_uint4(m.x != 0.f, m.y != 0.f, m.z != 0.f, m.w != 0.f);
    }
}

// ---------------------------------------------------------------------------
// K1: all four projections in ONE launch (grid.y selects A/W/C).
// 1024 blocks -> full occupancy (was 256 blocks = 1.7 blocks/SM).
// ---------------------------------------------------------------------------
__global__ __launch_bounds__(256) void gemm_proj4(const float* __restrict__ inQ,
                                                  const float* __restrict__ inK,
                                                  const float* __restrict__ inV,
                                                  const float* __restrict__ Wfc0,
                                                  const float* __restrict__ WQ,
                                                  const float* __restrict__ WK,
                                                  const float* __restrict__ WV)
{
    const float* A; const float* W; float* C;
    switch (blockIdx.y) {
        case 0:  A = inQ; W = Wfc0; C = g_R;  break;
        case 1:  A = inQ; W = WQ;   C = g_Qp; break;
        case 2:  A = inK; W = WK;   C = g_Kp; break;
        default: A = inV; W = WV;   C = g_Vp; break;
    }

    __shared__ float sA[64][36];
    __shared__ float sW[32][132];
    const int tid = threadIdx.x;
    const int tx = tid & 15, ty = tid >> 4;
    const int r0 = blockIdx.x * 64;

    float acc[4][8];
#pragma unroll
    for (int r = 0; r < 4; r++)
#pragma unroll
        for (int c = 0; c < 8; c++) acc[r][c] = 0.f;

    for (int kk = 0; kk < DM; kk += 32) {
        for (int t = tid; t < 64 * 32; t += 256) {
            int r = t >> 5, i = t & 31;
            sA[r][i] = A[(size_t)(r0 + r) * DM + kk + i];
        }
        for (int t = tid; t < 32 * 128; t += 256) {
            int i = t >> 7, c = t & 127;
            sW[i][c] = W[(size_t)(kk + i) * DM + c];
        }
        __syncthreads();
#pragma unroll
        for (int i = 0; i < 32; i++) {
            float a[4];
#pragma unroll
            for (int r = 0; r < 4; r++) a[r] = sA[ty * 4 + r][i];
            float4 w0 = *(const float4*)&sW[i][tx * 8];
            float4 w1 = *(const float4*)&sW[i][tx * 8 + 4];
            float w[8] = {w0.x, w0.y, w0.z, w0.w, w1.x, w1.y, w1.z, w1.w};
#pragma unroll
            for (int r = 0; r < 4; r++)
#pragma unroll
                for (int c = 0; c < 8; c++) acc[r][c] += a[r] * w[c];
        }
        __syncthreads();
    }
#pragma unroll
    for (int r = 0; r < 4; r++) {
        size_t row = (size_t)(r0 + ty * 4 + r);
        float4 o0 = make_float4(acc[r][0], acc[r][1], acc[r][2], acc[r][3]);
        float4 o1 = make_float4(acc[r][4], acc[r][5], acc[r][6], acc[r][7]);
        *(float4*)&C[row * DM + tx * 8]     = o0;
        *(float4*)&C[row * DM + tx * 8 + 4] = o1;
    }
}

// ---------------------------------------------------------------------------
// K2: single-pass attention. Per (b,h,q-tile): scores -> exp (unnormalized)
// -> write attn + accumulate rowsum + context. Context normalized at end.
// ---------------------------------------------------------------------------
__global__ __launch_bounds__(256) void attn_pass(const unsigned char* __restrict__ mask,
                                                 float* __restrict__ attn)
{
    extern __shared__ float sm[];
    float* sQt = sm + SQT_OFF;   // [32][132]  (d-major, q inner)
    float* sKt = sm + SKT_OFF;   // [32][68]
    float* sVt = sm + SVT_OFF;   // [32][68]
    float* sS  = sm + SS_OFF;    // [128][68]
    __shared__ float srinv[128];

    const int tid = threadIdx.x;
    const int tx = tid & 15, ty = tid >> 4;
    const int bh = blockIdx.y;
    const int b = bh >> 2, h = bh & 3;
    const int q0 = blockIdx.x * TQ;
    // fold softmax scale into log2(e): exp(s/sqrt(32)) = 2^(s*C)
    const float C = 1.4426950408889634f * 0.17677669529663689f;
    const int mmode = g_mask_mode;

    // load + transpose Q tile [128 q][32 d] -> sQt[d][q]
    const float* Qb = g_Qp + ((size_t)(b * SEQ + q0)) * DM + h * DKC;
    for (int t = tid; t < TQ * DKC; t += 256) {
        int q = t >> 5, d = t & 31;
        sQt[d * 132 + q] = Qb[(size_t)q * DM + d];
    }
    __syncthreads();

    float rowsum[8];
    float cacc[8][2];
#pragma unroll
    for (int a = 0; a < 8; a++) { rowsum[a] = 0.f; cacc[a][0] = 0.f; cacc[a][1] = 0.f; }

    for (int kc = 0; kc < SEQ / TK; kc++) {
        const int k0 = kc * TK;
        const float* Kb = g_Kp + ((size_t)(b * SEQ + k0)) * DM + h * DKC;
        const float* Vb = g_Vp + ((size_t)(b * SEQ + k0)) * DM + h * DKC;
        for (int t = tid; t < TK * DKC; t += 256) {
            int k = t >> 5, d = t & 31;
            sKt[d * 68 + k] = Kb[(size_t)k * DM + d];
            sVt[d * 68 + k] = Vb[(size_t)k * DM + d];
        }
        __syncthreads();

        // scores: 8q x 4k per thread, tile 128x64
        float acc[8][4];
#pragma unroll
        for (int a = 0; a < 8; a++)
#pragma unroll
            for (int c = 0; c < 4; c++) acc[a][c] = 0.f;

#pragma unroll 8
        for (int i = 0; i < DKC; i++) {
            float4 qa = *(const float4*)&sQt[i * 132 + ty * 8];
            float4 qb2 = *(const float4*)&sQt[i * 132 + ty * 8 + 4];
            float4 kv = *(const float4*)&sKt[i * 68 + tx * 4];
            float qs[8] = {qa.x, qa.y, qa.z, qa.w, qb2.x, qb2.y, qb2.z, qb2.w};
            float ks[4] = {kv.x, kv.y, kv.z, kv.w};
#pragma unroll
            for (int a = 0; a < 8; a++)
#pragma unroll
                for (int c = 0; c < 4; c++) acc[a][c] += qs[a] * ks[c];
        }

        // exp (FMA-pipe poly) + mask + store (unnormalized) to gmem + smem
#pragma unroll
        for (int a = 0; a < 8; a++) {
            const int q = q0 + ty * 8 + a;
            uint4 m4 = load_mask4(mask, ((size_t)b * SEQ + q) * SEQ + k0 + tx * 4, mmode);
            float e0 = m4.x ? 0.f : exp2_poly(acc[a][0] * C);
            float e1 = m4.y ? 0.f : exp2_poly(acc[a][1] * C);
            float e2 = m4.z ? 0.f : exp2_poly(acc[a][2] * C);
            float e3 = m4.w ? 0.f : exp2_poly(acc[a][3] * C);
            rowsum[a] += (e0 + e1) + (e2 + e3);
            float4 ev = make_float4(e0, e1, e2, e3);
            *(float4*)&sS[(ty * 8 + a) * 68 + tx * 4] = ev;
            *(float4*)(attn + (((size_t)bh * SEQ + q) * SEQ + k0 + tx * 4)) = ev;
        }
        __syncthreads();

        // context: 8q x 2d per thread (d = tx, tx+16), over 64 k
#pragma unroll 4
        for (int kk = 0; kk < TK; kk += 4) {
            float4 v0 = *(const float4*)&sVt[tx * 68 + kk];
            float4 v1 = *(const float4*)&sVt[(tx + 16) * 68 + kk];
#pragma unroll
            for (int a = 0; a < 8; a++) {
                float4 s4 = *(const float4*)&sS[(ty * 8 + a) * 68 + kk];
                cacc[a][0] += s4.x * v0.x; cacc[a][0] += s4.y * v0.y;
                cacc[a][0] += s4.z * v0.z; cacc[a][0] += s4.w * v0.w;
                cacc[a][1] += s4.x * v1.x; cacc[a][1] += s4.y * v1.y;
                cacc[a][1] += s4.z * v1.z; cacc[a][1] += s4.w * v1.w;
            }
        }
        __syncthreads();
    }

    // rowsum reduction across 16 tx lanes (reuse sS)
    float* red = sS;
#pragma unroll
    for (int a = 0; a < 8; a++) red[(ty * 8 + a) * 17 + tx] = rowsum[a];
    __syncthreads();
    if (tid < 128) {
        float s = 0.f;
#pragma unroll
        for (int j = 0; j < 16; j++) s += red[tid * 17 + j];
        float r = 1.0f / s;
        srinv[tid] = r;
        g_rinv[(size_t)bh * SEQ + q0 + tid] = r;
    }
    __syncthreads();

#pragma unroll
    for (int a = 0; a < 8; a++) {
        float r = srinv[ty * 8 + a];
        size_t o = ((size_t)(b * SEQ + q0 + ty * 8 + a)) * DM + h * DKC;
        g_ctx[o + tx]      = cacc[a][0] * r;
        g_ctx[o + tx + 16] = cacc[a][1] * r;
    }
}

// ---------------------------------------------------------------------------
// K3: attn *= rinv[row]   (1.07 GB streamed, float4)
// ---------------------------------------------------------------------------
__global__ void norm_attn(float* __restrict__ attn)
{
    size_t i = (size_t)blockIdx.x * blockDim.x + threadIdx.x;  // one float4 each
    size_t row = i >> 9;                                       // 512 float4 per row
    float r = __ldg(&g_rinv[row]);
    float4* p = (float4*)attn;
    float4 v = p[i];
    v.x *= r; v.y *= r; v.z *= r; v.w *= r;
    p[i] = v;
}

// ---------------------------------------------------------------------------
// K4: out = LayerNorm(g_ctx @ W_fc + g_R) * gamma + beta
// ---------------------------------------------------------------------------
__global__ __launch_bounds__(256) void out_ln(const float* __restrict__ Wfc,
                                              const float* __restrict__ gamma,
                                              const float* __restrict__ beta,
                                              float* __restrict__ out)
{
    __shared__ float sA[64][36];
    __shared__ float sW[32][132];
    __shared__ float red1[64][17];
    __shared__ float red2[64][17];
    __shared__ float smu[64];
    __shared__ float srs[64];

    const int tid = threadIdx.x;
    const int tx = tid & 15, ty = tid >> 4;
    const int r0 = blockIdx.x * 64;

    float acc[4][8];
#pragma unroll
    for (int r = 0; r < 4; r++)
#pragma unroll
        for (int c = 0; c < 8; c++) acc[r][c] = 0.f;

    for (int kk = 0; kk < DM; kk += 32) {
        for (int t = tid; t < 64 * 32; t += 256) {
            int r = t >> 5, i = t & 31;
            sA[r][i] = g_ctx[(size_t)(r0 + r) * DM + kk + i];
        }
        for (int t = tid; t < 32 * 128; t += 256) {
            int i = t >> 7, c = t & 127;
            sW[i][c] = Wfc[(size_t)(kk + i) * DM + c];
        }
        __syncthreads();
#pragma unroll
        for (int i = 0; i < 32; i++) {
            float a[4];
#pragma unroll
            for (int r = 0; r < 4; r++) a[r] = sA[ty * 4 + r][i];
            float4 w0 = *(const float4*)&sW[i][tx * 8];
            float4 w1 = *(const float4*)&sW[i][tx * 8 + 4];
            float w[8] = {w0.x, w0.y, w0.z, w0.w, w1.x, w1.y, w1.z, w1.w};
#pragma unroll
            for (int r = 0; r < 4; r++)
#pragma unroll
                for (int c = 0; c < 8; c++) acc[r][c] += a[r] * w[c];
        }
        __syncthreads();
    }

    // add residual, per-row partial moments
#pragma unroll
    for (int r = 0; r < 4; r++) {
        size_t row = (size_t)(r0 + ty * 4 + r);
        float4 rv0 = *(const float4*)&g_R[row * DM + tx * 8];
        float4 rv1 = *(const float4*)&g_R[row * DM + tx * 8 + 4];
        float rs[8] = {rv0.x, rv0.y, rv0.z, rv0.w, rv1.x, rv1.y, rv1.z, rv1.w};
        float ps = 0.f, pq = 0.f;
#pragma unroll
        for (int c = 0; c < 8; c++) {
            acc[r][c] += rs[c];
            ps += acc[r][c];
            pq += acc[r][c] * acc[r][c];
        }
        red1[ty * 4 + r][tx] = ps;
        red2[ty * 4 + r][tx] = pq;
    }
    __syncthreads();
    if (tid < 64) {
        float s = 0.f, q = 0.f;
#pragma unroll
        for (int j = 0; j < 16; j++) { s += red1[tid][j]; q += red2[tid][j]; }
        float mu = s * (1.0f / 128.0f);
        float var = q * (1.0f / 128.0f) - mu * mu;
        smu[tid] = mu;
        srs[tid] = rsqrtf(var + 1e-5f);
    }
    __syncthreads();

    float4 g0 = *(const float4*)&gamma[tx * 8];
    float4 g1 = *(const float4*)&gamma[tx * 8 + 4];
    float4 b0 = *(const float4*)&beta[tx * 8];
    float4 b1 = *(const float4*)&beta[tx * 8 + 4];
    float gs[8] = {g0.x, g0.y, g0.z, g0.w, g1.x, g1.y, g1.z, g1.w};
    float bs[8] = {b0.x, b0.y, b0.z, b0.w, b1.x, b1.y, b1.z, b1.w};

#pragma unroll
    for (int r = 0; r < 4; r++) {
        float mu = smu[ty * 4 + r];
        float rstd = srs[ty * 4 + r];
        size_t row = (size_t)(r0 + ty * 4 + r);
        float o[8];
#pragma unroll
        for (int c = 0; c < 8; c++) o[c] = (acc[r][c] - mu) * rstd * gs[c] + bs[c];
        *(float4*)&out[row * DM + tx * 8]     = make_float4(o[0], o[1], o[2], o[3]);
        *(float4*)&out[row * DM + tx * 8 + 4] = make_float4(o[4], o[5], o[6], o[7]);
    }
}

// ---------------------------------------------------------------------------
extern "C" void kernel_launch(void* const* d_in, const int* in_sizes, int n_in,
                              void* d_out, int out_size)
{
    const float* inQ  = (const float*)d_in[0];
    const float* inK  = (const float*)d_in[1];
    const float* inV  = (const float*)d_in[2];
    const unsigned char* mask = (const unsigned char*)d_in[3];
    const float* Wfc0 = (const float*)d_in[4];
    const float* WQ   = (const float*)d_in[5];
    const float* WK   = (const float*)d_in[6];
    const float* WV   = (const float*)d_in[7];
    const float* Wfc  = (const float*)d_in[8];
    const float* gam  = (const float*)d_in[9];
    const float* bet  = (const float*)d_in[10];
    float* out  = (float*)d_out;
    float* attn = out + OUT_ELEMS;

    // K0: mask dtype detection
    detect_mask<<<1, 256>>>(mask);

    // K1: all projections, one launch
    gemm_proj4<<<dim3(NR / 64, 4), 256>>>(inQ, inK, inV, Wfc0, WQ, WK, WV);

    // K2: attention (unnormalized attn write + context)
    cudaFuncSetAttribute(attn_pass, cudaFuncAttributeMaxDynamicSharedMemorySize,
                         (int)SMEM_BYTES);
    dim3 agrid(SEQ / TQ, BATCH * NH);
    attn_pass<<<agrid, 256, SMEM_BYTES>>>(mask, attn);

    // K3: normalize attn in place
    size_t nf4 = (size_t)BATCH * NH * SEQ * SEQ / 4;   // 33,554,432
    norm_attn<<<(unsigned)(nf4 / 256), 256>>>(attn);

    // K4: output projection + residual + LayerNorm
    out_ln<<<NR / 64, 256>>>(Wfc, gam, bet, out);
}

// round 4
// speedup vs baseline: 1.1051x; 1.1051x over previous
#include <cuda_runtime.h>
#include <cuda_bf16.h>
#include <stdint.h>

// ---------------------------------------------------------------------------
// MultiHeadAttention: out = LN(ctx@W_fc + X@W_fc0), attn materialized.
// B=8, S=2048, D=128, H=4, dk=dv=32.
// Output buffer layout: [out (8*2048*128)] then [attn (8*4*2048*2048)].
// K2 uses bf16 mma.sync (m16n8k16) with 2-term split x3 products (~fp32 acc).
// ---------------------------------------------------------------------------

namespace {
constexpr int BATCH = 8;
constexpr int SEQ   = 2048;
constexpr int DM    = 128;
constexpr int NR    = BATCH * SEQ;                 // 16384 rows
constexpr size_t OUT_ELEMS = (size_t)NR * DM;      // 2,097,152
constexpr int TQ = 128;                            // q-tile per block
constexpr int TK = 64;                             // k-chunk

// smem layout for attn kernel, in bf16 elements
constexpr int QSTR = 40;    // Q/K row stride (32 d + pad)  -> 20 words: conflict-free frags
constexpr int ESTR = 72;    // E/V row stride (64 j + pad)  -> 36 words: conflict-free frags
constexpr int QH_OFF = 0;                       // sQh[128][40]
constexpr int QL_OFF = QH_OFF + 128 * QSTR;     // sQl
constexpr int KH_OFF = QL_OFF + 128 * QSTR;     // sKh[64][40]
constexpr int KL_OFF = KH_OFF + 64 * QSTR;
constexpr int VH_OFF = KL_OFF + 64 * QSTR;      // sVh[32][72]  (v-major, j contiguous)
constexpr int VL_OFF = VH_OFF + 32 * ESTR;
constexpr int EH_OFF = VL_OFF + 32 * ESTR;      // sEh[128][72]
constexpr int EL_OFF = EH_OFF + 128 * ESTR;
constexpr int SMEM_BF16 = EL_OFF + 128 * ESTR;
constexpr size_t SMEM_BYTES = (size_t)SMEM_BF16 * 2;   // 76,800 B
}

// Scratch (device globals: allocation-free rule)
__device__ float g_R  [NR * DM];
__device__ float g_Qp [NR * DM];
__device__ float g_Kp [NR * DM];
__device__ float g_Vp [NR * DM];
__device__ float g_ctx[NR * DM];
__device__ float g_rinv[BATCH * 4 * SEQ];
__device__ int   g_mask_mode;   // 0=uint8, 1=int32, 2=float32

// ---------------------------------------------------------------------------
// fast exp2 (degree-5, FMA pipe), input pre-multiplied by log2(e)*scale.
// ---------------------------------------------------------------------------
__device__ __forceinline__ float exp2_poly(float y)
{
    float t   = __fadd_rn(y, 12582912.0f);         // 1.5*2^23 round trick
    float n_f = __fsub_rn(t, 12582912.0f);
    float r   = __fsub_rn(y, n_f);
    int   n   = __float_as_int(t) - 0x4B400000;
    float p   = 1.333355815e-3f;
    p = __fmaf_rn(p, r, 9.618129107e-3f);
    p = __fmaf_rn(p, r, 5.550410866e-2f);
    p = __fmaf_rn(p, r, 2.402265070e-1f);
    p = __fmaf_rn(p, r, 6.931471806e-1f);
    p = __fmaf_rn(p, r, 1.0f);
    return __int_as_float(__float_as_int(p) + (n << 23));
}

// pack two floats -> bf16x2 word (lo = first arg)
__device__ __forceinline__ uint32_t pack_bf16x2(float lo, float hi)
{
    uint32_t r;
    asm("cvt.rn.bf16x2.f32 %0, %1, %2;" : "=r"(r) : "f"(hi), "f"(lo));
    return r;
}
__device__ __forceinline__ float bf16_lo(uint32_t w) { return __uint_as_float(w << 16); }
__device__ __forceinline__ float bf16_hi(uint32_t w) { return __uint_as_float(w & 0xffff0000u); }

__device__ __forceinline__ void mma16816(float c[4],
                                         uint32_t a0, uint32_t a1, uint32_t a2, uint32_t a3,
                                         uint32_t b0, uint32_t b1)
{
    asm volatile("mma.sync.aligned.m16n8k16.row.col.f32.bf16.bf16.f32 "
                 "{%0,%1,%2,%3}, {%4,%5,%6,%7}, {%8,%9}, {%0,%1,%2,%3};"
                 : "+f"(c[0]), "+f"(c[1]), "+f"(c[2]), "+f"(c[3])
                 : "r"(a0), "r"(a1), "r"(a2), "r"(a3), "r"(b0), "r"(b1));
}

// ---------------------------------------------------------------------------
// K0: detect mask dtype from byte patterns in the first 4096 bytes.
// ---------------------------------------------------------------------------
__global__ void detect_mask(const unsigned char* __restrict__ m)
{
    __shared__ int s_gt1, s_off;
    if (threadIdx.x == 0) { s_gt1 = 0; s_off = 0; }
    __syncthreads();
    int gt1 = 0, off = 0;
    for (int i = threadIdx.x; i < 4096; i += 256) {
        unsigned char v = m[i];
        if (v > 1) gt1 = 1;
        else if (v == 1 && (i & 3) != 0) off = 1;
    }
    if (gt1) atomicOr(&s_gt1, 1);
    if (off) atomicOr(&s_off, 1);
    __syncthreads();
    if (threadIdx.x == 0)
        g_mask_mode = s_gt1 ? 2 : (s_off ? 0 : 1);
}

// load 2 consecutive mask flags at element index idx (idx even)
__device__ __forceinline__ uint2 load_mask2(const unsigned char* __restrict__ mask,
                                            size_t idx, int mode)
{
    if (mode == 0) {
        uchar2 m = *(const uchar2*)(mask + idx);
        return make_uint2(m.x, m.y);
    } else if (mode == 1) {
        int2 m = *(const int2*)((const int*)mask + idx);
        return make_uint2((unsigned)m.x, (unsigned)m.y);
    } else {
        float2 m = *(const float2*)((const float*)mask + idx);
        return make_uint2(m.x != 0.f, m.y != 0.f);
    }
}

// ---------------------------------------------------------------------------
// K1: all four projections in ONE launch (grid.y selects A/W/C).
// ---------------------------------------------------------------------------
__global__ __launch_bounds__(256) void gemm_proj4(const float* __restrict__ inQ,
                                                  const float* __restrict__ inK,
                                                  const float* __restrict__ inV,
                                                  const float* __restrict__ Wfc0,
                                                  const float* __restrict__ WQ,
                                                  const float* __restrict__ WK,
                                                  const float* __restrict__ WV)
{
    const float* A; const float* W; float* C;
    switch (blockIdx.y) {
        case 0:  A = inQ; W = Wfc0; C = g_R;  break;
        case 1:  A = inQ; W = WQ;   C = g_Qp; break;
        case 2:  A = inK; W = WK;   C = g_Kp; break;
        default: A = inV; W = WV;   C = g_Vp; break;
    }

    __shared__ float sA[64][36];
    __shared__ float sW[32][132];
    const int tid = threadIdx.x;
    const int tx = tid & 15, ty = tid >> 4;
    const int r0 = blockIdx.x * 64;

    float acc[4][8];
#pragma unroll
    for (int r = 0; r < 4; r++)
#pragma unroll
        for (int c = 0; c < 8; c++) acc[r][c] = 0.f;

    for (int kk = 0; kk < DM; kk += 32) {
        for (int t = tid; t < 64 * 32; t += 256) {
            int r = t >> 5, i = t & 31;
            sA[r][i] = A[(size_t)(r0 + r) * DM + kk + i];
        }
        for (int t = tid; t < 32 * 128; t += 256) {
            int i = t >> 7, c = t & 127;
            sW[i][c] = W[(size_t)(kk + i) * DM + c];
        }
        __syncthreads();
#pragma unroll
        for (int i = 0; i < 32; i++) {
            float a[4];
#pragma unroll
            for (int r = 0; r < 4; r++) a[r] = sA[ty * 4 + r][i];
            float4 w0 = *(const float4*)&sW[i][tx * 8];
            float4 w1 = *(const float4*)&sW[i][tx * 8 + 4];
            float w[8] = {w0.x, w0.y, w0.z, w0.w, w1.x, w1.y, w1.z, w1.w};
#pragma unroll
            for (int r = 0; r < 4; r++)
#pragma unroll
                for (int c = 0; c < 8; c++) acc[r][c] += a[r] * w[c];
        }
        __syncthreads();
    }
#pragma unroll
    for (int r = 0; r < 4; r++) {
        size_t row = (size_t)(r0 + ty * 4 + r);
        *(float4*)&C[row * DM + tx * 8]     = make_float4(acc[r][0], acc[r][1], acc[r][2], acc[r][3]);
        *(float4*)&C[row * DM + tx * 8 + 4] = make_float4(acc[r][4], acc[r][5], acc[r][6], acc[r][7]);
    }
}

// ---------------------------------------------------------------------------
// split x (fp32) into bf16 hi/lo, store into two bf16 smem arrays
// ---------------------------------------------------------------------------
__device__ __forceinline__ void split_store(__nv_bfloat16* sh, __nv_bfloat16* sl,
                                            int idx, float x)
{
    uint32_t hb = __float_as_uint(x);
    uint32_t rr = hb + 0x7fffu + ((hb >> 16) & 1u);  // rn to bf16
    uint32_t hw = rr & 0xffff0000u;
    float hf = __uint_as_float(hw);
    float lf = x - hf;
    ((uint16_t*)sh)[idx] = (uint16_t)(hw >> 16);
    uint32_t lb = __float_as_uint(lf);
    uint32_t lr = (lb + 0x7fffu + ((lb >> 16) & 1u)) >> 16;
    ((uint16_t*)sl)[idx] = (uint16_t)lr;
}

// ---------------------------------------------------------------------------
// K2: tensor-core attention. Per (b,h,q-tile=128): loop k-chunks of 64:
//  scores via 3x-split bf16 MMA -> mask+exp -> E (bf16 hi/lo in smem, fp32 to
//  gmem unnormalized) -> context via 3x-split bf16 MMA. Normalize ctx at end.
// ---------------------------------------------------------------------------
__global__ __launch_bounds__(256) void attn_mma(const unsigned char* __restrict__ mask,
                                                float* __restrict__ attn)
{
    extern __shared__ __nv_bfloat16 smb[];
    __nv_bfloat16* sQh = smb + QH_OFF;
    __nv_bfloat16* sQl = smb + QL_OFF;
    __nv_bfloat16* sKh = smb + KH_OFF;
    __nv_bfloat16* sKl = smb + KL_OFF;
    __nv_bfloat16* sVh = smb + VH_OFF;
    __nv_bfloat16* sVl = smb + VL_OFF;
    __nv_bfloat16* sEh = smb + EH_OFF;
    __nv_bfloat16* sEl = smb + EL_OFF;
    __shared__ float srow[128];

    const int tid  = threadIdx.x;
    const int w    = tid >> 5;
    const int lane = tid & 31;
    const int g    = lane >> 2;       // group id 0..7
    const int tig  = lane & 3;        // thread in group
    const int qb   = w * 16;          // warp's q-row base in tile

    const int bh = blockIdx.y;
    const int b = bh >> 2, h = bh & 3;
    const int q0 = blockIdx.x * TQ;
    const float CE = 1.4426950408889634f * 0.17677669529663689f; // log2e/sqrt(32)
    const int mmode = g_mask_mode;
    const size_t bS = (size_t)b * SEQ;

    // ---- load Q tile (128x32) once, split hi/lo ----
    {
        const float* Qb = g_Qp + (bS + q0) * DM + h * 32;
        for (int t = tid; t < 128 * 32; t += 256) {
            int q = t >> 5, d = t & 31;
            split_store(sQh, sQl, q * QSTR + d, Qb[(size_t)q * DM + d]);
        }
    }

    float rs0 = 0.f, rs1 = 0.f;        // rowsums for q=qb+g, qb+g+8
    float cacc[4][4];                  // ctx accum: 4 n-tiles (32 v) x 4 frag regs
#pragma unroll
    for (int n = 0; n < 4; n++)
#pragma unroll
        for (int i = 0; i < 4; i++) cacc[n][i] = 0.f;

    for (int kc = 0; kc < SEQ / TK; kc++) {
        const int k0 = kc * TK;
        __syncthreads();  // protect K/V/E regions from previous iteration readers

        // ---- load K tile (64x32) and V tile transposed (32v x 64j), split ----
        {
            const float* Kb = g_Kp + (bS + k0) * DM + h * 32;
            for (int t = tid; t < 64 * 32; t += 256) {
                int j = t >> 5, d = t & 31;
                split_store(sKh, sKl, j * QSTR + d, Kb[(size_t)j * DM + d]);
            }
            const float* Vb = g_Vp + (bS + k0) * DM + h * 32;
            for (int t = tid; t < 64 * 32; t += 256) {
                int j = t >> 5, v = t & 31;
                split_store(sVh, sVl, v * ESTR + j, Vb[(size_t)j * DM + v]);
            }
        }
        __syncthreads();

        // ---- score phase: S[128q x 64j] = Q K^T ----
        // A fragments (Q) hoisted: kk in {0,16}
        uint32_t qh[2][4], ql[2][4];
#pragma unroll
        for (int kk = 0; kk < 2; kk++) {
            int c0 = kk * 16 + tig * 2;
            qh[kk][0] = *(const uint32_t*)&sQh[(qb + g) * QSTR + c0];
            qh[kk][1] = *(const uint32_t*)&sQh[(qb + g + 8) * QSTR + c0];
            qh[kk][2] = *(const uint32_t*)&sQh[(qb + g) * QSTR + c0 + 8];
            qh[kk][3] = *(const uint32_t*)&sQh[(qb + g + 8) * QSTR + c0 + 8];
            ql[kk][0] = *(const uint32_t*)&sQl[(qb + g) * QSTR + c0];
            ql[kk][1] = *(const uint32_t*)&sQl[(qb + g + 8) * QSTR + c0];
            ql[kk][2] = *(const uint32_t*)&sQl[(qb + g) * QSTR + c0 + 8];
            ql[kk][3] = *(const uint32_t*)&sQl[(qb + g + 8) * QSTR + c0 + 8];
        }

#pragma unroll
        for (int nt = 0; nt < 8; nt++) {
            const int j0 = nt * 8;
            float c[4] = {0.f, 0.f, 0.f, 0.f};
#pragma unroll
            for (int kk = 0; kk < 2; kk++) {
                int dof = kk * 16 + tig * 2;
                uint32_t bh0 = *(const uint32_t*)&sKh[(j0 + g) * QSTR + dof];
                uint32_t bh1 = *(const uint32_t*)&sKh[(j0 + g) * QSTR + dof + 8];
                uint32_t bl0 = *(const uint32_t*)&sKl[(j0 + g) * QSTR + dof];
                uint32_t bl1 = *(const uint32_t*)&sKl[(j0 + g) * QSTR + dof + 8];
                mma16816(c, qh[kk][0], qh[kk][1], qh[kk][2], qh[kk][3], bh0, bh1);
                mma16816(c, qh[kk][0], qh[kk][1], qh[kk][2], qh[kk][3], bl0, bl1);
                mma16816(c, ql[kk][0], ql[kk][1], ql[kk][2], ql[kk][3], bh0, bh1);
            }
            // epilogue: mask + exp + rowsum + split-store E
            const int jl = j0 + tig * 2;       // local key col (even)
            const int jgl = k0 + jl;
            const int qg0 = q0 + qb + g;
            uint2 m0 = load_mask2(mask, (bS + qg0) * SEQ + jgl, mmode);
            uint2 m1 = load_mask2(mask, (bS + qg0 + 8) * SEQ + jgl, mmode);
            float e00 = m0.x ? 0.f : exp2_poly(c[0] * CE);
            float e01 = m0.y ? 0.f : exp2_poly(c[1] * CE);
            float e10 = m1.x ? 0.f : exp2_poly(c[2] * CE);
            float e11 = m1.y ? 0.f : exp2_poly(c[3] * CE);
            rs0 += e00 + e01;
            rs1 += e10 + e11;
            uint32_t hw0 = pack_bf16x2(e00, e01);
            uint32_t hw1 = pack_bf16x2(e10, e11);
            uint32_t lw0 = pack_bf16x2(e00 - bf16_lo(hw0), e01 - bf16_hi(hw0));
            uint32_t lw1 = pack_bf16x2(e10 - bf16_lo(hw1), e11 - bf16_hi(hw1));
            *(uint32_t*)&sEh[(qb + g) * ESTR + jl]     = hw0;
            *(uint32_t*)&sEh[(qb + g + 8) * ESTR + jl] = hw1;
            *(uint32_t*)&sEl[(qb + g) * ESTR + jl]     = lw0;
            *(uint32_t*)&sEl[(qb + g + 8) * ESTR + jl] = lw1;
        }
        __syncthreads();

        // ---- context phase: ctx[128q x 32v] += E[128x64] V[64x32] ----
#pragma unroll
        for (int jj = 0; jj < 4; jj++) {
            int c0 = jj * 16 + tig * 2;
            uint32_t ah0 = *(const uint32_t*)&sEh[(qb + g) * ESTR + c0];
            uint32_t ah1 = *(const uint32_t*)&sEh[(qb + g + 8) * ESTR + c0];
            uint32_t ah2 = *(const uint32_t*)&sEh[(qb + g) * ESTR + c0 + 8];
            uint32_t ah3 = *(const uint32_t*)&sEh[(qb + g + 8) * ESTR + c0 + 8];
            uint32_t al0 = *(const uint32_t*)&sEl[(qb + g) * ESTR + c0];
            uint32_t al1 = *(const uint32_t*)&sEl[(qb + g + 8) * ESTR + c0];
            uint32_t al2 = *(const uint32_t*)&sEl[(qb + g) * ESTR + c0 + 8];
            uint32_t al3 = *(const uint32_t*)&sEl[(qb + g + 8) * ESTR + c0 + 8];
#pragma unroll
            for (int nt = 0; nt < 4; nt++) {
                int v0 = nt * 8;
                uint32_t bh0 = *(const uint32_t*)&sVh[(v0 + g) * ESTR + c0];
                uint32_t bh1 = *(const uint32_t*)&sVh[(v0 + g) * ESTR + c0 + 8];
                uint32_t bl0 = *(const uint32_t*)&sVl[(v0 + g) * ESTR + c0];
                uint32_t bl1 = *(const uint32_t*)&sVl[(v0 + g) * ESTR + c0 + 8];
                mma16816(cacc[nt], ah0, ah1, ah2, ah3, bh0, bh1);
                mma16816(cacc[nt], ah0, ah1, ah2, ah3, bl0, bl1);
                mma16816(cacc[nt], al0, al1, al2, al3, bh0, bh1);
            }
        }

        // ---- coalesced attn writeback (reconstruct fp32 = hi + lo) ----
        {
            int q = tid >> 1;
            int jc = (tid & 1) * 32;
            size_t gbase = ((size_t)bh * SEQ + q0 + q) * SEQ + k0 + jc;
#pragma unroll
            for (int i = 0; i < 8; i++) {
                int jl = jc + i * 4;
                uint32_t h0 = *(const uint32_t*)&sEh[q * ESTR + jl];
                uint32_t h1 = *(const uint32_t*)&sEh[q * ESTR + jl + 2];
                uint32_t l0 = *(const uint32_t*)&sEl[q * ESTR + jl];
                uint32_t l1 = *(const uint32_t*)&sEl[q * ESTR + jl + 2];
                float4 ev;
                ev.x = bf16_lo(h0) + bf16_lo(l0);
                ev.y = bf16_hi(h0) + bf16_hi(l0);
                ev.z = bf16_lo(h1) + bf16_lo(l1);
                ev.w = bf16_hi(h1) + bf16_hi(l1);
                *(float4*)(attn + gbase + i * 4) = ev;
            }
        }
    }

    // ---- rowsum reduction and rinv ----
    rs0 += __shfl_xor_sync(0xffffffff, rs0, 1);
    rs0 += __shfl_xor_sync(0xffffffff, rs0, 2);
    rs1 += __shfl_xor_sync(0xffffffff, rs1, 1);
    rs1 += __shfl_xor_sync(0xffffffff, rs1, 2);
    __syncthreads();
    if (tig == 0) {
        srow[qb + g]     = rs0;
        srow[qb + g + 8] = rs1;
    }
    __syncthreads();
    if (tid < 128) {
        float r = 1.0f / srow[tid];
        g_rinv[(size_t)bh * SEQ + q0 + tid] = r;
        srow[tid] = r;
    }
    __syncthreads();

    // ---- normalized context write ----
    {
        float r0 = srow[qb + g];
        float r1 = srow[qb + g + 8];
        size_t row0 = (bS + q0 + qb + g) * (size_t)DM + h * 32;
        size_t row1 = row0 + 8 * DM;
#pragma unroll
        for (int nt = 0; nt < 4; nt++) {
            int v = nt * 8 + tig * 2;
            *(float2*)&g_ctx[row0 + v] = make_float2(cacc[nt][0] * r0, cacc[nt][1] * r0);
            *(float2*)&g_ctx[row1 + v] = make_float2(cacc[nt][2] * r1, cacc[nt][3] * r1);
        }
    }
}

// ---------------------------------------------------------------------------
// K3: attn *= rinv[row]
// ---------------------------------------------------------------------------
__global__ void norm_attn(float* __restrict__ attn)
{
    size_t i = (size_t)blockIdx.x * blockDim.x + threadIdx.x;
    size_t row = i >> 9;
    float r = __ldg(&g_rinv[row]);
    float4* p = (float4*)attn;
    float4 v = p[i];
    v.x *= r; v.y *= r; v.z *= r; v.w *= r;
    p[i] = v;
}

// ---------------------------------------------------------------------------
// K4: out = LayerNorm(g_ctx @ W_fc + g_R) * gamma + beta
// ---------------------------------------------------------------------------
__global__ __launch_bounds__(256) void out_ln(const float* __restrict__ Wfc,
                                              const float* __restrict__ gamma,
                                              const float* __restrict__ beta,
                                              float* __restrict__ out)
{
    __shared__ float sA[64][36];
    __shared__ float sW[32][132];
    __shared__ float red1[64][17];
    __shared__ float red2[64][17];
    __shared__ float smu[64];
    __shared__ float srs[64];

    const int tid = threadIdx.x;
    const int tx = tid & 15, ty = tid >> 4;
    const int r0 = blockIdx.x * 64;

    float acc[4][8];
#pragma unroll
    for (int r = 0; r < 4; r++)
#pragma unroll
        for (int c = 0; c < 8; c++) acc[r][c] = 0.f;

    for (int kk = 0; kk < DM; kk += 32) {
        for (int t = tid; t < 64 * 32; t += 256) {
            int r = t >> 5, i = t & 31;
            sA[r][i] = g_ctx[(size_t)(r0 + r) * DM + kk + i];
        }
        for (int t = tid; t < 32 * 128; t += 256) {
            int i = t >> 7, c = t & 127;
            sW[i][c] = Wfc[(size_t)(kk + i) * DM + c];
        }
        __syncthreads();
#pragma unroll
        for (int i = 0; i < 32; i++) {
            float a[4];
#pragma unroll
            for (int r = 0; r < 4; r++) a[r] = sA[ty * 4 + r][i];
            float4 w0 = *(const float4*)&sW[i][tx * 8];
            float4 w1 = *(const float4*)&sW[i][tx * 8 + 4];
            float wv[8] = {w0.x, w0.y, w0.z, w0.w, w1.x, w1.y, w1.z, w1.w};
#pragma unroll
            for (int r = 0; r < 4; r++)
#pragma unroll
                for (int c = 0; c < 8; c++) acc[r][c] += a[r] * wv[c];
        }
        __syncthreads();
    }

#pragma unroll
    for (int r = 0; r < 4; r++) {
        size_t row = (size_t)(r0 + ty * 4 + r);
        float4 rv0 = *(const float4*)&g_R[row * DM + tx * 8];
        float4 rv1 = *(const float4*)&g_R[row * DM + tx * 8 + 4];
        float rsv[8] = {rv0.x, rv0.y, rv0.z, rv0.w, rv1.x, rv1.y, rv1.z, rv1.w};
        float ps = 0.f, pq = 0.f;
#pragma unroll
        for (int c = 0; c < 8; c++) {
            acc[r][c] += rsv[c];
            ps += acc[r][c];
            pq += acc[r][c] * acc[r][c];
        }
        red1[ty * 4 + r][tx] = ps;
        red2[ty * 4 + r][tx] = pq;
    }
    __syncthreads();
    if (tid < 64) {
        float s = 0.f, q = 0.f;
#pragma unroll
        for (int j = 0; j < 16; j++) { s += red1[tid][j]; q += red2[tid][j]; }
        float mu = s * (1.0f / 128.0f);
        float var = q * (1.0f / 128.0f) - mu * mu;
        smu[tid] = mu;
        srs[tid] = rsqrtf(var + 1e-5f);
    }
    __syncthreads();

    float4 g0 = *(const float4*)&gamma[tx * 8];
    float4 g1 = *(const float4*)&gamma[tx * 8 + 4];
    float4 b0 = *(const float4*)&beta[tx * 8];
    float4 b1 = *(const float4*)&beta[tx * 8 + 4];
    float gs[8] = {g0.x, g0.y, g0.z, g0.w, g1.x, g1.y, g1.z, g1.w};
    float bs[8] = {b0.x, b0.y, b0.z, b0.w, b1.x, b1.y, b1.z, b1.w};

#pragma unroll
    for (int r = 0; r < 4; r++) {
        float mu = smu[ty * 4 + r];
        float rstd = srs[ty * 4 + r];
        size_t row = (size_t)(r0 + ty * 4 + r);
        float o[8];
#pragma unroll
        for (int c = 0; c < 8; c++) o[c] = (acc[r][c] - mu) * rstd * gs[c] + bs[c];
        *(float4*)&out[row * DM + tx * 8]     = make_float4(o[0], o[1], o[2], o[3]);
        *(float4*)&out[row * DM + tx * 8 + 4] = make_float4(o[4], o[5], o[6], o[7]);
    }
}

// ---------------------------------------------------------------------------
extern "C" void kernel_launch(void* const* d_in, const int* in_sizes, int n_in,
                              void* d_out, int out_size)
{
    const float* inQ  = (const float*)d_in[0];
    const float* inK  = (const float*)d_in[1];
    const float* inV  = (const float*)d_in[2];
    const unsigned char* mask = (const unsigned char*)d_in[3];
    const float* Wfc0 = (const float*)d_in[4];
    const float* WQ   = (const float*)d_in[5];
    const float* WK   = (const float*)d_in[6];
    const float* WV   = (const float*)d_in[7];
    const float* Wfc  = (const float*)d_in[8];
    const float* gam  = (const float*)d_in[9];
    const float* bet  = (const float*)d_in[10];
    float* out  = (float*)d_out;
    float* attn = out + OUT_ELEMS;

    detect_mask<<<1, 256>>>(mask);

    gemm_proj4<<<dim3(NR / 64, 4), 256>>>(inQ, inK, inV, Wfc0, WQ, WK, WV);

    cudaFuncSetAttribute(attn_mma, cudaFuncAttributeMaxDynamicSharedMemorySize,
                         (int)SMEM_BYTES);
    dim3 agrid(SEQ / TQ, BATCH * 4);
    attn_mma<<<agrid, 256, SMEM_BYTES>>>(mask, attn);

    size_t nf4 = (size_t)BATCH * 4 * SEQ * SEQ / 4;
    norm_attn<<<(unsigned)(nf4 / 256), 256>>>(attn);

    out_ln<<<NR / 64, 256>>>(Wfc, gam, bet, out);
}

// round 5
// speedup vs baseline: 1.3470x; 1.2188x over previous
#include <cuda_runtime.h>
#include <cuda_bf16.h>
#include <stdint.h>

// ---------------------------------------------------------------------------
// MultiHeadAttention: out = LN(ctx@W_fc + X@W_fc0), attn materialized.
// B=8, S=2048, D=128, H=4, dk=dv=32.
// Output buffer layout: [out (8*2048*128)] then [attn (8*4*2048*2048)].
// K2: bf16 mma.sync, 3x-split QK^T scores; E kept in registers and fed
// straight into the ctx MMA as A-fragments (no smem round-trip).
// ---------------------------------------------------------------------------

namespace {
constexpr int BATCH = 8;
constexpr int SEQ   = 2048;
constexpr int DM    = 128;
constexpr int NR    = BATCH * SEQ;                 // 16384 rows
constexpr size_t OUT_ELEMS = (size_t)NR * DM;      // 2,097,152
constexpr int TQ = 128;                            // q-tile per block
constexpr int TK = 64;                             // k-chunk

// smem layout for attn kernel, in bf16 elements
constexpr int QSTR = 40;    // Q/K row stride (32 d + pad): conflict-free frags
constexpr int ESTR = 72;    // V row stride (64 j + pad): conflict-free frags
constexpr int QH_OFF = 0;                       // sQh[128][40]
constexpr int QL_OFF = QH_OFF + 128 * QSTR;     // sQl[128][40]
constexpr int KH_OFF = QL_OFF + 128 * QSTR;     // sKh[64][40]
constexpr int KL_OFF = KH_OFF + 64 * QSTR;      // sKl[64][40]
constexpr int VH_OFF = KL_OFF + 64 * QSTR;      // sVh[32][72] (v-major)
constexpr int SMEM_BF16 = VH_OFF + 32 * ESTR;
constexpr size_t SMEM_BYTES = (size_t)SMEM_BF16 * 2;   // 35,328 B
}

// Scratch (device globals: allocation-free rule)
__device__ float g_R  [NR * DM];
__device__ float g_Qp [NR * DM];
__device__ float g_Kp [NR * DM];
__device__ float g_Vp [NR * DM];
__device__ float g_ctx[NR * DM];
__device__ float g_rinv[BATCH * 4 * SEQ];
__device__ int   g_mask_mode;   // 0=uint8, 1=int32, 2=float32

// ---------------------------------------------------------------------------
// fast exp2 (degree-5, FMA pipe), input pre-multiplied by log2(e)*scale.
// ---------------------------------------------------------------------------
__device__ __forceinline__ float exp2_poly(float y)
{
    float t   = __fadd_rn(y, 12582912.0f);         // 1.5*2^23 round trick
    float n_f = __fsub_rn(t, 12582912.0f);
    float r   = __fsub_rn(y, n_f);
    int   n   = __float_as_int(t) - 0x4B400000;
    float p   = 1.333355815e-3f;
    p = __fmaf_rn(p, r, 9.618129107e-3f);
    p = __fmaf_rn(p, r, 5.550410866e-2f);
    p = __fmaf_rn(p, r, 2.402265070e-1f);
    p = __fmaf_rn(p, r, 6.931471806e-1f);
    p = __fmaf_rn(p, r, 1.0f);
    return __int_as_float(__float_as_int(p) + (n << 23));
}

// pack two floats -> bf16x2 word (lo half = first arg)
__device__ __forceinline__ uint32_t pack_bf16x2(float lo, float hi)
{
    uint32_t r;
    asm("cvt.rn.bf16x2.f32 %0, %1, %2;" : "=r"(r) : "f"(hi), "f"(lo));
    return r;
}

__device__ __forceinline__ void mma16816(float c[4],
                                         uint32_t a0, uint32_t a1, uint32_t a2, uint32_t a3,
                                         uint32_t b0, uint32_t b1)
{
    asm volatile("mma.sync.aligned.m16n8k16.row.col.f32.bf16.bf16.f32 "
                 "{%0,%1,%2,%3}, {%4,%5,%6,%7}, {%8,%9}, {%0,%1,%2,%3};"
                 : "+f"(c[0]), "+f"(c[1]), "+f"(c[2]), "+f"(c[3])
                 : "r"(a0), "r"(a1), "r"(a2), "r"(a3), "r"(b0), "r"(b1));
}

// ---------------------------------------------------------------------------
// K0: detect mask dtype from byte patterns in the first 4096 bytes.
// ---------------------------------------------------------------------------
__global__ void detect_mask(const unsigned char* __restrict__ m)
{
    __shared__ int s_gt1, s_off;
    if (threadIdx.x == 0) { s_gt1 = 0; s_off = 0; }
    __syncthreads();
    int gt1 = 0, off = 0;
    for (int i = threadIdx.x; i < 4096; i += 256) {
        unsigned char v = m[i];
        if (v > 1) gt1 = 1;
        else if (v == 1 && (i & 3) != 0) off = 1;
    }
    if (gt1) atomicOr(&s_gt1, 1);
    if (off) atomicOr(&s_off, 1);
    __syncthreads();
    if (threadIdx.x == 0)
        g_mask_mode = s_gt1 ? 2 : (s_off ? 0 : 1);
}

// K0b: tiny filler (also shifts ncu capture window onto attn_mma)
__global__ void zero_rinv()
{
    g_rinv[blockIdx.x * 256 + threadIdx.x] = 0.f;
}

// load 2 consecutive mask flags at element index idx (idx even)
__device__ __forceinline__ uint2 load_mask2(const unsigned char* __restrict__ mask,
                                            size_t idx, int mode)
{
    if (mode == 0) {
        uchar2 m = *(const uchar2*)(mask + idx);
        return make_uint2(m.x, m.y);
    } else if (mode == 1) {
        int2 m = *(const int2*)((const int*)mask + idx);
        return make_uint2((unsigned)m.x, (unsigned)m.y);
    } else {
        float2 m = *(const float2*)((const float*)mask + idx);
        return make_uint2(m.x != 0.f, m.y != 0.f);
    }
}

// ---------------------------------------------------------------------------
// K1: all four projections in ONE launch (grid.y selects A/W/C).
// ---------------------------------------------------------------------------
__global__ __launch_bounds__(256) void gemm_proj4(const float* __restrict__ inQ,
                                                  const float* __restrict__ inK,
                                                  const float* __restrict__ inV,
                                                  const float* __restrict__ Wfc0,
                                                  const float* __restrict__ WQ,
                                                  const float* __restrict__ WK,
                                                  const float* __restrict__ WV)
{
    const float* A; const float* W; float* C;
    switch (blockIdx.y) {
        case 0:  A = inQ; W = Wfc0; C = g_R;  break;
        case 1:  A = inQ; W = WQ;   C = g_Qp; break;
        case 2:  A = inK; W = WK;   C = g_Kp; break;
        default: A = inV; W = WV;   C = g_Vp; break;
    }

    __shared__ float sA[64][36];
    __shared__ float sW[32][132];
    const int tid = threadIdx.x;
    const int tx = tid & 15, ty = tid >> 4;
    const int r0 = blockIdx.x * 64;

    float acc[4][8];
#pragma unroll
    for (int r = 0; r < 4; r++)
#pragma unroll
        for (int c = 0; c < 8; c++) acc[r][c] = 0.f;

    for (int kk = 0; kk < DM; kk += 32) {
        for (int t = tid; t < 64 * 32; t += 256) {
            int r = t >> 5, i = t & 31;
            sA[r][i] = A[(size_t)(r0 + r) * DM + kk + i];
        }
        for (int t = tid; t < 32 * 128; t += 256) {
            int i = t >> 7, c = t & 127;
            sW[i][c] = W[(size_t)(kk + i) * DM + c];
        }
        __syncthreads();
#pragma unroll
        for (int i = 0; i < 32; i++) {
            float a[4];
#pragma unroll
            for (int r = 0; r < 4; r++) a[r] = sA[ty * 4 + r][i];
            float4 w0 = *(const float4*)&sW[i][tx * 8];
            float4 w1 = *(const float4*)&sW[i][tx * 8 + 4];
            float w[8] = {w0.x, w0.y, w0.z, w0.w, w1.x, w1.y, w1.z, w1.w};
#pragma unroll
            for (int r = 0; r < 4; r++)
#pragma unroll
                for (int c = 0; c < 8; c++) acc[r][c] += a[r] * w[c];
        }
        __syncthreads();
    }
#pragma unroll
    for (int r = 0; r < 4; r++) {
        size_t row = (size_t)(r0 + ty * 4 + r);
        *(float4*)&C[row * DM + tx * 8]     = make_float4(acc[r][0], acc[r][1], acc[r][2], acc[r][3]);
        *(float4*)&C[row * DM + tx * 8 + 4] = make_float4(acc[r][4], acc[r][5], acc[r][6], acc[r][7]);
    }
}

// ---------------------------------------------------------------------------
// split x (fp32) into bf16 hi/lo, store into two bf16 smem arrays
// ---------------------------------------------------------------------------
__device__ __forceinline__ void split_store(__nv_bfloat16* sh, __nv_bfloat16* sl,
                                            int idx, float x)
{
    uint32_t hb = __float_as_uint(x);
    uint32_t rr = hb + 0x7fffu + ((hb >> 16) & 1u);  // rn to bf16
    uint32_t hw = rr & 0xffff0000u;
    float hf = __uint_as_float(hw);
    float lf = x - hf;
    ((uint16_t*)sh)[idx] = (uint16_t)(hw >> 16);
    uint32_t lb = __float_as_uint(lf);
    uint32_t lr = (lb + 0x7fffu + ((lb >> 16) & 1u)) >> 16;
    ((uint16_t*)sl)[idx] = (uint16_t)lr;
}

__device__ __forceinline__ void bf16_store(__nv_bfloat16* sh, int idx, float x)
{
    uint32_t hb = __float_as_uint(x);
    uint32_t hw = (hb + 0x7fffu + ((hb >> 16) & 1u)) >> 16;
    ((uint16_t*)sh)[idx] = (uint16_t)hw;
}

// ---------------------------------------------------------------------------
// K2: tensor-core attention. Per (b,h,q-tile=128), loop k-chunks of 64:
//  scores via 3x-split bf16 MMA -> mask+exp -> attn fp32 direct from frags,
//  E packed to bf16 in registers -> ctx MMA (A-frag = score frag layout).
// ---------------------------------------------------------------------------
__global__ __launch_bounds__(256) void attn_mma(const unsigned char* __restrict__ mask,
                                                float* __restrict__ attn)
{
    extern __shared__ __nv_bfloat16 smb[];
    __nv_bfloat16* sQh = smb + QH_OFF;
    __nv_bfloat16* sQl = smb + QL_OFF;
    __nv_bfloat16* sKh = smb + KH_OFF;
    __nv_bfloat16* sKl = smb + KL_OFF;
    __nv_bfloat16* sVh = smb + VH_OFF;
    __shared__ float srow[128];

    const int tid  = threadIdx.x;
    const int w    = tid >> 5;
    const int lane = tid & 31;
    const int g    = lane >> 2;       // group id 0..7
    const int tig  = lane & 3;        // thread in group
    const int qb   = w * 16;          // warp's q-row base in tile

    const int bh = blockIdx.y;
    const int b = bh >> 2, h = bh & 3;
    const int q0 = blockIdx.x * TQ;
    const float CE = 1.4426950408889634f * 0.17677669529663689f; // log2e/sqrt(32)
    const int mmode = g_mask_mode;
    const size_t bS = (size_t)b * SEQ;

    // ---- load Q tile (128x32) once, split hi/lo ----
    {
        const float* Qb = g_Qp + (bS + q0) * DM + h * 32;
        for (int t = tid; t < 128 * 32; t += 256) {
            int q = t >> 5, d = t & 31;
            split_store(sQh, sQl, q * QSTR + d, Qb[(size_t)q * DM + d]);
        }
    }

    float rs0 = 0.f, rs1 = 0.f;        // rowsums for q = qb+g, qb+g+8
    float cacc[4][4];                  // ctx accum: 4 v-tiles x 4 frag regs
#pragma unroll
    for (int n = 0; n < 4; n++)
#pragma unroll
        for (int i = 0; i < 4; i++) cacc[n][i] = 0.f;

    // rows this thread owns in score/ctx fragments
    const int qg0 = q0 + qb + g;
    const size_t arow0 = ((size_t)bh * SEQ + qg0) * SEQ;
    const size_t arow1 = arow0 + 8 * SEQ;
    const size_t mrow0 = (bS + qg0) * SEQ;
    const size_t mrow1 = mrow0 + 8 * SEQ;

    for (int kc = 0; kc < SEQ / TK; kc++) {
        const int k0 = kc * TK;
        __syncthreads();  // all warps done reading previous K/V tiles

        // ---- load K tile (64x32, split hi/lo) and V tile (32v x 64j, hi) ----
        {
            const float* Kb = g_Kp + (bS + k0) * DM + h * 32;
            for (int t = tid; t < 64 * 32; t += 256) {
                int j = t >> 5, d = t & 31;
                split_store(sKh, sKl, j * QSTR + d, Kb[(size_t)j * DM + d]);
            }
            const float* Vb = g_Vp + (bS + k0) * DM + h * 32;
            for (int t = tid; t < 64 * 32; t += 256) {
                int j = t >> 5, v = t & 31;
                bf16_store(sVh, v * ESTR + j, Vb[(size_t)j * DM + v]);
            }
        }
        __syncthreads();

        // ---- Q fragments hoisted (kk in {0,16}) ----
        uint32_t qh[2][4], ql[2][4];
#pragma unroll
        for (int kk = 0; kk < 2; kk++) {
            int c0 = kk * 16 + tig * 2;
            qh[kk][0] = *(const uint32_t*)&sQh[(qb + g) * QSTR + c0];
            qh[kk][1] = *(const uint32_t*)&sQh[(qb + g + 8) * QSTR + c0];
            qh[kk][2] = *(const uint32_t*)&sQh[(qb + g) * QSTR + c0 + 8];
            qh[kk][3] = *(const uint32_t*)&sQh[(qb + g + 8) * QSTR + c0 + 8];
            ql[kk][0] = *(const uint32_t*)&sQl[(qb + g) * QSTR + c0];
            ql[kk][1] = *(const uint32_t*)&sQl[(qb + g + 8) * QSTR + c0];
            ql[kk][2] = *(const uint32_t*)&sQl[(qb + g) * QSTR + c0 + 8];
            ql[kk][3] = *(const uint32_t*)&sQl[(qb + g + 8) * QSTR + c0 + 8];
        }

#pragma unroll
        for (int jj = 0; jj < 4; jj++) {
            uint32_t eh[2][2];   // E bf16x2 frags: [sub-tile][row0/row1]
#pragma unroll
            for (int s = 0; s < 2; s++) {
                const int nt = jj * 2 + s;
                const int j0 = nt * 8;
                float c[4] = {0.f, 0.f, 0.f, 0.f};
#pragma unroll
                for (int kk = 0; kk < 2; kk++) {
                    int dof = kk * 16 + tig * 2;
                    uint32_t bh0 = *(const uint32_t*)&sKh[(j0 + g) * QSTR + dof];
                    uint32_t bh1 = *(const uint32_t*)&sKh[(j0 + g) * QSTR + dof + 8];
                    uint32_t bl0 = *(const uint32_t*)&sKl[(j0 + g) * QSTR + dof];
                    uint32_t bl1 = *(const uint32_t*)&sKl[(j0 + g) * QSTR + dof + 8];
                    mma16816(c, qh[kk][0], qh[kk][1], qh[kk][2], qh[kk][3], bh0, bh1);
                    mma16816(c, qh[kk][0], qh[kk][1], qh[kk][2], qh[kk][3], bl0, bl1);
                    mma16816(c, ql[kk][0], ql[kk][1], ql[kk][2], ql[kk][3], bh0, bh1);
                }
                // epilogue: mask + exp + rowsum + direct attn store + pack E
                const int jl = j0 + tig * 2;
                const int jgl = k0 + jl;
                uint2 m0 = load_mask2(mask, mrow0 + jgl, mmode);
                uint2 m1 = load_mask2(mask, mrow1 + jgl, mmode);
                float e00 = m0.x ? 0.f : exp2_poly(c[0] * CE);
                float e01 = m0.y ? 0.f : exp2_poly(c[1] * CE);
                float e10 = m1.x ? 0.f : exp2_poly(c[2] * CE);
                float e11 = m1.y ? 0.f : exp2_poly(c[3] * CE);
                rs0 += e00 + e01;
                rs1 += e10 + e11;
                *(float2*)(attn + arow0 + jgl) = make_float2(e00, e01);
                *(float2*)(attn + arow1 + jgl) = make_float2(e10, e11);
                eh[s][0] = pack_bf16x2(e00, e01);
                eh[s][1] = pack_bf16x2(e10, e11);
            }
            // ---- ctx MMA: A-frag == score frag layout for k-block jj*16 ----
            const int c0 = jj * 16 + tig * 2;
#pragma unroll
            for (int nt2 = 0; nt2 < 4; nt2++) {
                int v0 = nt2 * 8;
                uint32_t vb0 = *(const uint32_t*)&sVh[(v0 + g) * ESTR + c0];
                uint32_t vb1 = *(const uint32_t*)&sVh[(v0 + g) * ESTR + c0 + 8];
                mma16816(cacc[nt2], eh[0][0], eh[0][1], eh[1][0], eh[1][1], vb0, vb1);
            }
        }
    }

    // ---- rowsum reduction and rinv ----
    rs0 += __shfl_xor_sync(0xffffffff, rs0, 1);
    rs0 += __shfl_xor_sync(0xffffffff, rs0, 2);
    rs1 += __shfl_xor_sync(0xffffffff, rs1, 1);
    rs1 += __shfl_xor_sync(0xffffffff, rs1, 2);
    __syncthreads();
    if (tig == 0) {
        srow[qb + g]     = rs0;
        srow[qb + g + 8] = rs1;
    }
    __syncthreads();
    if (tid < 128) {
        float r = 1.0f / srow[tid];
        g_rinv[(size_t)bh * SEQ + q0 + tid] = r;
        srow[tid] = r;
    }
    __syncthreads();

    // ---- normalized context write ----
    {
        float r0 = srow[qb + g];
        float r1 = srow[qb + g + 8];
        size_t row0 = (bS + q0 + qb + g) * (size_t)DM + h * 32;
        size_t row1 = row0 + 8 * DM;
#pragma unroll
        for (int nt = 0; nt < 4; nt++) {
            int v = nt * 8 + tig * 2;
            *(float2*)&g_ctx[row0 + v] = make_float2(cacc[nt][0] * r0, cacc[nt][1] * r0);
            *(float2*)&g_ctx[row1 + v] = make_float2(cacc[nt][2] * r1, cacc[nt][3] * r1);
        }
    }
}

// ---------------------------------------------------------------------------
// K3: attn *= rinv[row]
// ---------------------------------------------------------------------------
__global__ void norm_attn(float* __restrict__ attn)
{
    size_t i = (size_t)blockIdx.x * blockDim.x + threadIdx.x;
    size_t row = i >> 9;
    float r = __ldg(&g_rinv[row]);
    float4* p = (float4*)attn;
    float4 v = p[i];
    v.x *= r; v.y *= r; v.z *= r; v.w *= r;
    p[i] = v;
}

// ---------------------------------------------------------------------------
// K4: out = LayerNorm(g_ctx @ W_fc + g_R) * gamma + beta
// ---------------------------------------------------------------------------
__global__ __launch_bounds__(256) void out_ln(const float* __restrict__ Wfc,
                                              const float* __restrict__ gamma,
                                              const float* __restrict__ beta,
                                              float* __restrict__ out)
{
    __shared__ float sA[64][36];
    __shared__ float sW[32][132];
    __shared__ float red1[64][17];
    __shared__ float red2[64][17];
    __shared__ float smu[64];
    __shared__ float srs[64];

    const int tid = threadIdx.x;
    const int tx = tid & 15, ty = tid >> 4;
    const int r0 = blockIdx.x * 64;

    float acc[4][8];
#pragma unroll
    for (int r = 0; r < 4; r++)
#pragma unroll
        for (int c = 0; c < 8; c++) acc[r][c] = 0.f;

    for (int kk = 0; kk < DM; kk += 32) {
        for (int t = tid; t < 64 * 32; t += 256) {
            int r = t >> 5, i = t & 31;
            sA[r][i] = g_ctx[(size_t)(r0 + r) * DM + kk + i];
        }
        for (int t = tid; t < 32 * 128; t += 256) {
            int i = t >> 7, c = t & 127;
            sW[i][c] = Wfc[(size_t)(kk + i) * DM + c];
        }
        __syncthreads();
#pragma unroll
        for (int i = 0; i < 32; i++) {
            float a[4];
#pragma unroll
            for (int r = 0; r < 4; r++) a[r] = sA[ty * 4 + r][i];
            float4 w0 = *(const float4*)&sW[i][tx * 8];
            float4 w1 = *(const float4*)&sW[i][tx * 8 + 4];
            float wv[8] = {w0.x, w0.y, w0.z, w0.w, w1.x, w1.y, w1.z, w1.w};
#pragma unroll
            for (int r = 0; r < 4; r++)
#pragma unroll
                for (int c = 0; c < 8; c++) acc[r][c] += a[r] * wv[c];
        }
        __syncthreads();
    }

#pragma unroll
    for (int r = 0; r < 4; r++) {
        size_t row = (size_t)(r0 + ty * 4 + r);
        float4 rv0 = *(const float4*)&g_R[row * DM + tx * 8];
        float4 rv1 = *(const float4*)&g_R[row * DM + tx * 8 + 4];
        float rsv[8] = {rv0.x, rv0.y, rv0.z, rv0.w, rv1.x, rv1.y, rv1.z, rv1.w};
        float ps = 0.f, pq = 0.f;
#pragma unroll
        for (int c = 0; c < 8; c++) {
            acc[r][c] += rsv[c];
            ps += acc[r][c];
            pq += acc[r][c] * acc[r][c];
        }
        red1[ty * 4 + r][tx] = ps;
        red2[ty * 4 + r][tx] = pq;
    }
    __syncthreads();
    if (tid < 64) {
        float s = 0.f, q = 0.f;
#pragma unroll
        for (int j = 0; j < 16; j++) { s += red1[tid][j]; q += red2[tid][j]; }
        float mu = s * (1.0f / 128.0f);
        float var = q * (1.0f / 128.0f) - mu * mu;
        smu[tid] = mu;
        srs[tid] = rsqrtf(var + 1e-5f);
    }
    __syncthreads();

    float4 g0 = *(const float4*)&gamma[tx * 8];
    float4 g1 = *(const float4*)&gamma[tx * 8 + 4];
    float4 b0 = *(const float4*)&beta[tx * 8];
    float4 b1 = *(const float4*)&beta[tx * 8 + 4];
    float gs[8] = {g0.x, g0.y, g0.z, g0.w, g1.x, g1.y, g1.z, g1.w};
    float bs[8] = {b0.x, b0.y, b0.z, b0.w, b1.x, b1.y, b1.z, b1.w};

#pragma unroll
    for (int r = 0; r < 4; r++) {
        float mu = smu[ty * 4 + r];
        float rstd = srs[ty * 4 + r];
        size_t row = (size_t)(r0 + ty * 4 + r);
        float o[8];
#pragma unroll
        for (int c = 0; c < 8; c++) o[c] = (acc[r][c] - mu) * rstd * gs[c] + bs[c];
        *(float4*)&out[row * DM + tx * 8]     = make_float4(o[0], o[1], o[2], o[3]);
        *(float4*)&out[row * DM + tx * 8 + 4] = make_float4(o[4], o[5], o[6], o[7]);
    }
}

// ---------------------------------------------------------------------------
extern "C" void kernel_launch(void* const* d_in, const int* in_sizes, int n_in,
                              void* d_out, int out_size)
{
    const float* inQ  = (const float*)d_in[0];
    const float* inK  = (const float*)d_in[1];
    const float* inV  = (const float*)d_in[2];
    const unsigned char* mask = (const unsigned char*)d_in[3];
    const float* Wfc0 = (const float*)d_in[4];
    const float* WQ   = (const float*)d_in[5];
    const float* WK   = (const float*)d_in[6];
    const float* WV   = (const float*)d_in[7];
    const float* Wfc  = (const float*)d_in[8];
    const float* gam  = (const float*)d_in[9];
    const float* bet  = (const float*)d_in[10];
    float* out  = (float*)d_out;
    float* attn = out + OUT_ELEMS;

    detect_mask<<<1, 256>>>(mask);
    zero_rinv<<<BATCH * 4 * SEQ / 256, 256>>>();   // filler: shifts ncu window

    gemm_proj4<<<dim3(NR / 64, 4), 256>>>(inQ, inK, inV, Wfc0, WQ, WK, WV);

    cudaFuncSetAttribute(attn_mma, cudaFuncAttributeMaxDynamicSharedMemorySize,
                         (int)SMEM_BYTES);
    dim3 agrid(SEQ / TQ, BATCH * 4);
    attn_mma<<<agrid, 256, SMEM_BYTES>>>(mask, attn);

    size_t nf4 = (size_t)BATCH * 4 * SEQ * SEQ / 4;
    norm_attn<<<(unsigned)(nf4 / 256), 256>>>(attn);

    out_ln<<<NR / 64, 256>>>(Wfc, gam, bet, out);
}

// round 6
// speedup vs baseline: 1.6647x; 1.2359x over previous
#include <cuda_runtime.h>
#include <cuda_bf16.h>
#include <stdint.h>

// ---------------------------------------------------------------------------
// MultiHeadAttention: out = LN(ctx@W_fc + X@W_fc0), attn materialized.
// B=8, S=2048, D=128, H=4, dk=dv=32.
// Output layout: [out (8*2048*128)] then [attn (8*4*2048*2048)].
// K2: bf16 mma.sync; Q/K pre-split to bf16 hi/lo in the projection kernel;
// double-buffered K/V smem (1 barrier/chunk); mask prefetch; E in registers.
// ---------------------------------------------------------------------------

namespace {
constexpr int BATCH = 8;
constexpr int SEQ   = 2048;
constexpr int DM    = 128;
constexpr int NR    = BATCH * SEQ;                 // 16384 rows
constexpr size_t OUT_ELEMS = (size_t)NR * DM;      // 2,097,152
constexpr int TQ = 128;                            // q-tile per block
constexpr int TK = 64;                             // k-chunk

// smem (bf16 units)
constexpr int QSTR = 40;    // Q/K row stride (32 + pad): conflict-free frags
constexpr int ESTR = 72;    // V row stride (64 + pad): conflict-free frags
constexpr int QH_OFF  = 0;                         // sQh[128][40]
constexpr int QL_OFF  = QH_OFF + 128 * QSTR;       // sQl[128][40]
constexpr int BUF_OFF = QL_OFF + 128 * QSTR;       // double-buffered K/V
constexpr int BUF_SZ  = 64 * QSTR * 2 + 32 * ESTR; // KH + KL + VH = 7424
constexpr int SMEM_BF16 = BUF_OFF + 2 * BUF_SZ;    // 25088
constexpr size_t SMEM_BYTES = (size_t)SMEM_BF16 * 2;  // 50,176 B
}

// Scratch (device globals: allocation-free rule)
__device__ float g_R  [NR * DM];
__device__ float g_ctx[NR * DM];
__device__ float g_rinv[BATCH * 4 * SEQ];
__device__ __nv_bfloat16 g_Qh[NR * DM];
__device__ __nv_bfloat16 g_Ql[NR * DM];
__device__ __nv_bfloat16 g_Kh[NR * DM];
__device__ __nv_bfloat16 g_Kl[NR * DM];
__device__ __nv_bfloat16 g_Vh[NR * DM];
__device__ int   g_mask_mode;   // 0=uint8, 1=int32, 2=float32

// ---------------------------------------------------------------------------
__device__ __forceinline__ float exp2_poly(float y)
{
    float t   = __fadd_rn(y, 12582912.0f);         // 1.5*2^23 round trick
    float n_f = __fsub_rn(t, 12582912.0f);
    float r   = __fsub_rn(y, n_f);
    int   n   = __float_as_int(t) - 0x4B400000;
    float p   = 1.333355815e-3f;
    p = __fmaf_rn(p, r, 9.618129107e-3f);
    p = __fmaf_rn(p, r, 5.550410866e-2f);
    p = __fmaf_rn(p, r, 2.402265070e-1f);
    p = __fmaf_rn(p, r, 6.931471806e-1f);
    p = __fmaf_rn(p, r, 1.0f);
    return __int_as_float(__float_as_int(p) + (n << 23));
}

__device__ __forceinline__ uint32_t pack_bf16x2(float lo, float hi)
{
    uint32_t r;
    asm("cvt.rn.bf16x2.f32 %0, %1, %2;" : "=r"(r) : "f"(hi), "f"(lo));
    return r;
}

__device__ __forceinline__ uint32_t bf16_rn_bits(float x)
{
    uint32_t b = __float_as_uint(x);
    return (b + 0x7fffu + ((b >> 16) & 1u)) >> 16;
}

__device__ __forceinline__ void mma16816(float c[4],
                                         uint32_t a0, uint32_t a1, uint32_t a2, uint32_t a3,
                                         uint32_t b0, uint32_t b1)
{
    asm volatile("mma.sync.aligned.m16n8k16.row.col.f32.bf16.bf16.f32 "
                 "{%0,%1,%2,%3}, {%4,%5,%6,%7}, {%8,%9}, {%0,%1,%2,%3};"
                 : "+f"(c[0]), "+f"(c[1]), "+f"(c[2]), "+f"(c[3])
                 : "r"(a0), "r"(a1), "r"(a2), "r"(a3), "r"(b0), "r"(b1));
}

// ---------------------------------------------------------------------------
// K0: detect mask dtype from byte patterns in the first 4096 bytes.
// ---------------------------------------------------------------------------
__global__ void detect_mask(const unsigned char* __restrict__ m)
{
    __shared__ int s_gt1, s_off;
    if (threadIdx.x == 0) { s_gt1 = 0; s_off = 0; }
    __syncthreads();
    int gt1 = 0, off = 0;
    for (int i = threadIdx.x; i < 4096; i += 256) {
        unsigned char v = m[i];
        if (v > 1) gt1 = 1;
        else if (v == 1 && (i & 3) != 0) off = 1;
    }
    if (gt1) atomicOr(&s_gt1, 1);
    if (off) atomicOr(&s_off, 1);
    __syncthreads();
    if (threadIdx.x == 0)
        g_mask_mode = s_gt1 ? 2 : (s_off ? 0 : 1);
}

// K0b: tiny filler (keeps ncu capture window on attn_mma)
__global__ void zero_rinv()
{
    g_rinv[blockIdx.x * 256 + threadIdx.x] = 0.f;
}

__device__ __forceinline__ uint2 load_mask2(const unsigned char* __restrict__ mask,
                                            size_t idx, int mode)
{
    if (mode == 0) {
        uchar2 m = *(const uchar2*)(mask + idx);
        return make_uint2(m.x, m.y);
    } else if (mode == 1) {
        int2 m = *(const int2*)((const int*)mask + idx);
        return make_uint2((unsigned)m.x, (unsigned)m.y);
    } else {
        float2 m = *(const float2*)((const float*)mask + idx);
        return make_uint2(m.x != 0.f, m.y != 0.f);
    }
}

// ---------------------------------------------------------------------------
// K1: four projections in one launch. Writes R (fp32), Q/K (bf16 hi+lo),
// V (bf16 hi) — the splits are computed ONCE here instead of per q-tile in K2.
// ---------------------------------------------------------------------------
__global__ __launch_bounds__(256) void gemm_proj4(const float* __restrict__ inQ,
                                                  const float* __restrict__ inK,
                                                  const float* __restrict__ inV,
                                                  const float* __restrict__ Wfc0,
                                                  const float* __restrict__ WQ,
                                                  const float* __restrict__ WK,
                                                  const float* __restrict__ WV)
{
    const float* A; const float* W;
    switch (blockIdx.y) {
        case 0:  A = inQ; W = Wfc0; break;
        case 1:  A = inQ; W = WQ;   break;
        case 2:  A = inK; W = WK;   break;
        default: A = inV; W = WV;   break;
    }

    __shared__ float sA[64][36];
    __shared__ float sW[32][132];
    const int tid = threadIdx.x;
    const int tx = tid & 15, ty = tid >> 4;
    const int r0 = blockIdx.x * 64;

    float acc[4][8];
#pragma unroll
    for (int r = 0; r < 4; r++)
#pragma unroll
        for (int c = 0; c < 8; c++) acc[r][c] = 0.f;

    for (int kk = 0; kk < DM; kk += 32) {
        for (int t = tid; t < 64 * 32; t += 256) {
            int r = t >> 5, i = t & 31;
            sA[r][i] = A[(size_t)(r0 + r) * DM + kk + i];
        }
        for (int t = tid; t < 32 * 128; t += 256) {
            int i = t >> 7, c = t & 127;
            sW[i][c] = W[(size_t)(kk + i) * DM + c];
        }
        __syncthreads();
#pragma unroll
        for (int i = 0; i < 32; i++) {
            float a[4];
#pragma unroll
            for (int r = 0; r < 4; r++) a[r] = sA[ty * 4 + r][i];
            float4 w0 = *(const float4*)&sW[i][tx * 8];
            float4 w1 = *(const float4*)&sW[i][tx * 8 + 4];
            float wv[8] = {w0.x, w0.y, w0.z, w0.w, w1.x, w1.y, w1.z, w1.w};
#pragma unroll
            for (int r = 0; r < 4; r++)
#pragma unroll
                for (int c = 0; c < 8; c++) acc[r][c] += a[r] * wv[c];
        }
        __syncthreads();
    }

#pragma unroll
    for (int r = 0; r < 4; r++) {
        size_t row = (size_t)(r0 + ty * 4 + r);
        size_t off = row * DM + tx * 8;
        if (blockIdx.y == 0) {
            *(float4*)&g_R[off]     = make_float4(acc[r][0], acc[r][1], acc[r][2], acc[r][3]);
            *(float4*)&g_R[off + 4] = make_float4(acc[r][4], acc[r][5], acc[r][6], acc[r][7]);
        } else if (blockIdx.y == 3) {
            uint32_t wv[4];
#pragma unroll
            for (int c2 = 0; c2 < 4; c2++)
                wv[c2] = bf16_rn_bits(acc[r][2 * c2]) | (bf16_rn_bits(acc[r][2 * c2 + 1]) << 16);
            *(uint4*)&g_Vh[off] = make_uint4(wv[0], wv[1], wv[2], wv[3]);
        } else {
            __nv_bfloat16* H = (blockIdx.y == 1) ? g_Qh : g_Kh;
            __nv_bfloat16* L = (blockIdx.y == 1) ? g_Ql : g_Kl;
            uint32_t hw[4], lw[4];
#pragma unroll
            for (int c2 = 0; c2 < 4; c2++) {
                uint32_t h0 = bf16_rn_bits(acc[r][2 * c2]);
                uint32_t h1 = bf16_rn_bits(acc[r][2 * c2 + 1]);
                float l0 = acc[r][2 * c2]     - __uint_as_float(h0 << 16);
                float l1 = acc[r][2 * c2 + 1] - __uint_as_float(h1 << 16);
                hw[c2] = h0 | (h1 << 16);
                lw[c2] = bf16_rn_bits(l0) | (bf16_rn_bits(l1) << 16);
            }
            *(uint4*)&H[off] = make_uint4(hw[0], hw[1], hw[2], hw[3]);
            *(uint4*)&L[off] = make_uint4(lw[0], lw[1], lw[2], lw[3]);
        }
    }
}

// ---------------------------------------------------------------------------
// K2: tensor-core attention, double-buffered K/V, mask prefetch.
// ---------------------------------------------------------------------------
__global__ __launch_bounds__(256, 3) void attn_mma(const unsigned char* __restrict__ mask,
                                                   float* __restrict__ attn)
{
    extern __shared__ __nv_bfloat16 smb[];
    __nv_bfloat16* sQh = smb + QH_OFF;
    __nv_bfloat16* sQl = smb + QL_OFF;
    __shared__ float srow[128];

    const int tid  = threadIdx.x;
    const int w    = tid >> 5;
    const int lane = tid & 31;
    const int g    = lane >> 2;
    const int tig  = lane & 3;
    const int qb   = w * 16;

    const int bh = blockIdx.y;
    const int b = bh >> 2, h = bh & 3;
    const int q0 = blockIdx.x * TQ;
    const float CE = 1.4426950408889634f * 0.17677669529663689f; // log2e/sqrt(32)
    const int mmode = g_mask_mode;
    const size_t bS = (size_t)b * SEQ;

    // copy indices for K/V tiles
    const int jj4  = tid >> 2;            // j row 0..63
    const int seg4 = (tid & 3) * 8;       // 0,8,16,24

    // ---- preload chunk 0 (gmem -> regs) ----
    uint4 rKh, rKl, rVh;
    {
        size_t base = (bS + jj4) * DM + h * 32 + seg4;
        rKh = *(const uint4*)&g_Kh[base];
        rKl = *(const uint4*)&g_Kl[base];
        rVh = *(const uint4*)&g_Vh[base];
    }

    // ---- copy Q tile (bf16, pre-split) ----
    {
        int q = tid >> 1, dseg = (tid & 1) * 16;
        size_t src = (bS + q0 + q) * DM + h * 32 + dseg;
        *(uint4*)&sQh[q * QSTR + dseg]     = *(const uint4*)&g_Qh[src];
        *(uint4*)&sQh[q * QSTR + dseg + 8] = *(const uint4*)&g_Qh[src + 8];
        *(uint4*)&sQl[q * QSTR + dseg]     = *(const uint4*)&g_Ql[src];
        *(uint4*)&sQl[q * QSTR + dseg + 8] = *(const uint4*)&g_Ql[src + 8];
    }

    // ---- store chunk 0 into buffer 0 ----
    {
        __nv_bfloat16* kh = smb + BUF_OFF;
        __nv_bfloat16* kl = kh + 64 * QSTR;
        __nv_bfloat16* vh = kl + 64 * QSTR;
        *(uint4*)&kh[jj4 * QSTR + seg4] = rKh;
        *(uint4*)&kl[jj4 * QSTR + seg4] = rKl;
        const uint16_t* vv = (const uint16_t*)&rVh;
#pragma unroll
        for (int i = 0; i < 8; i++)
            ((uint16_t*)vh)[(seg4 + i) * ESTR + jj4] = vv[i];
    }
    __syncthreads();

    // ---- Q fragments (loop-invariant) ----
    uint32_t qh[2][4], ql[2][4];
#pragma unroll
    for (int kk = 0; kk < 2; kk++) {
        int c0 = kk * 16 + tig * 2;
        qh[kk][0] = *(const uint32_t*)&sQh[(qb + g) * QSTR + c0];
        qh[kk][1] = *(const uint32_t*)&sQh[(qb + g + 8) * QSTR + c0];
        qh[kk][2] = *(const uint32_t*)&sQh[(qb + g) * QSTR + c0 + 8];
        qh[kk][3] = *(const uint32_t*)&sQh[(qb + g + 8) * QSTR + c0 + 8];
        ql[kk][0] = *(const uint32_t*)&sQl[(qb + g) * QSTR + c0];
        ql[kk][1] = *(const uint32_t*)&sQl[(qb + g + 8) * QSTR + c0];
        ql[kk][2] = *(const uint32_t*)&sQl[(qb + g) * QSTR + c0 + 8];
        ql[kk][3] = *(const uint32_t*)&sQl[(qb + g + 8) * QSTR + c0 + 8];
    }

    float rs0 = 0.f, rs1 = 0.f;
    float cacc[4][4];
#pragma unroll
    for (int n = 0; n < 4; n++)
#pragma unroll
        for (int i = 0; i < 4; i++) cacc[n][i] = 0.f;

    const int qg0 = q0 + qb + g;
    const size_t arow0 = ((size_t)bh * SEQ + qg0) * SEQ;
    const size_t arow1 = arow0 + 8 * SEQ;
    const size_t mrow0 = (bS + qg0) * SEQ;
    const size_t mrow1 = mrow0 + 8 * SEQ;

    for (int kc = 0; kc < SEQ / TK; kc++) {
        const int buf = kc & 1;
        const int k0 = kc * TK;
        __nv_bfloat16* kh = smb + BUF_OFF + buf * BUF_SZ;
        __nv_bfloat16* kl = kh + 64 * QSTR;
        __nv_bfloat16* vh = kl + 64 * QSTR;

        if (kc) {
            // store prefetched chunk kc into its buffer; barrier(kc-1) already
            // separated this write from all readers of this buffer.
            *(uint4*)&kh[jj4 * QSTR + seg4] = rKh;
            *(uint4*)&kl[jj4 * QSTR + seg4] = rKl;
            const uint16_t* vv = (const uint16_t*)&rVh;
#pragma unroll
            for (int i = 0; i < 8; i++)
                ((uint16_t*)vh)[(seg4 + i) * ESTR + jj4] = vv[i];
            __syncthreads();
        }
        if (kc < SEQ / TK - 1) {
            size_t base = (bS + k0 + TK + jj4) * DM + h * 32 + seg4;
            rKh = *(const uint4*)&g_Kh[base];
            rKl = *(const uint4*)&g_Kl[base];
            rVh = *(const uint4*)&g_Vh[base];
        }

        // mask prefetch for jj = 0
        uint2 pmc[4], pmn[4];
        pmc[0] = load_mask2(mask, mrow0 + k0 + tig * 2, mmode);
        pmc[1] = load_mask2(mask, mrow1 + k0 + tig * 2, mmode);
        pmc[2] = load_mask2(mask, mrow0 + k0 + 8 + tig * 2, mmode);
        pmc[3] = load_mask2(mask, mrow1 + k0 + 8 + tig * 2, mmode);

#pragma unroll
        for (int jj = 0; jj < 4; jj++) {
            if (jj < 3) {
                const int jn = (jj + 1) * 16 + tig * 2;
                pmn[0] = load_mask2(mask, mrow0 + k0 + jn, mmode);
                pmn[1] = load_mask2(mask, mrow1 + k0 + jn, mmode);
                pmn[2] = load_mask2(mask, mrow0 + k0 + jn + 8, mmode);
                pmn[3] = load_mask2(mask, mrow1 + k0 + jn + 8, mmode);
            }
            uint32_t eh[2][2];
#pragma unroll
            for (int s = 0; s < 2; s++) {
                const int j0 = jj * 16 + s * 8;
                float c[4] = {0.f, 0.f, 0.f, 0.f};
#pragma unroll
                for (int kk = 0; kk < 2; kk++) {
                    int dof = kk * 16 + tig * 2;
                    uint32_t bh0 = *(const uint32_t*)&kh[(j0 + g) * QSTR + dof];
                    uint32_t bh1 = *(const uint32_t*)&kh[(j0 + g) * QSTR + dof + 8];
                    uint32_t bl0 = *(const uint32_t*)&kl[(j0 + g) * QSTR + dof];
                    uint32_t bl1 = *(const uint32_t*)&kl[(j0 + g) * QSTR + dof + 8];
                    mma16816(c, qh[kk][0], qh[kk][1], qh[kk][2], qh[kk][3], bh0, bh1);
                    mma16816(c, qh[kk][0], qh[kk][1], qh[kk][2], qh[kk][3], bl0, bl1);
                    mma16816(c, ql[kk][0], ql[kk][1], ql[kk][2], ql[kk][3], bh0, bh1);
                }
                const int jl = j0 + tig * 2;
                const int jgl = k0 + jl;
                uint2 m0 = pmc[s * 2];
                uint2 m1 = pmc[s * 2 + 1];
                float e00 = m0.x ? 0.f : exp2_poly(c[0] * CE);
                float e01 = m0.y ? 0.f : exp2_poly(c[1] * CE);
                float e10 = m1.x ? 0.f : exp2_poly(c[2] * CE);
                float e11 = m1.y ? 0.f : exp2_poly(c[3] * CE);
                rs0 += e00 + e01;
                rs1 += e10 + e11;
                *(float2*)(attn + arow0 + jgl) = make_float2(e00, e01);
                *(float2*)(attn + arow1 + jgl) = make_float2(e10, e11);
                eh[s][0] = pack_bf16x2(e00, e01);
                eh[s][1] = pack_bf16x2(e10, e11);
            }
            const int c0 = jj * 16 + tig * 2;
#pragma unroll
            for (int nt2 = 0; nt2 < 4; nt2++) {
                int v0 = nt2 * 8;
                uint32_t vb0 = *(const uint32_t*)&vh[(v0 + g) * ESTR + c0];
                uint32_t vb1 = *(const uint32_t*)&vh[(v0 + g) * ESTR + c0 + 8];
                mma16816(cacc[nt2], eh[0][0], eh[0][1], eh[1][0], eh[1][1], vb0, vb1);
            }
#pragma unroll
            for (int i = 0; i < 4; i++) pmc[i] = pmn[i];
        }
    }

    // ---- rowsum reduction and rinv ----
    rs0 += __shfl_xor_sync(0xffffffff, rs0, 1);
    rs0 += __shfl_xor_sync(0xffffffff, rs0, 2);
    rs1 += __shfl_xor_sync(0xffffffff, rs1, 1);
    rs1 += __shfl_xor_sync(0xffffffff, rs1, 2);
    __syncthreads();
    if (tig == 0) {
        srow[qb + g]     = rs0;
        srow[qb + g + 8] = rs1;
    }
    __syncthreads();
    if (tid < 128) {
        float r = 1.0f / srow[tid];
        g_rinv[(size_t)bh * SEQ + q0 + tid] = r;
        srow[tid] = r;
    }
    __syncthreads();

    // ---- normalized context write ----
    {
        float r0 = srow[qb + g];
        float r1 = srow[qb + g + 8];
        size_t row0 = (bS + q0 + qb + g) * (size_t)DM + h * 32;
        size_t row1 = row0 + 8 * DM;
#pragma unroll
        for (int nt = 0; nt < 4; nt++) {
            int v = nt * 8 + tig * 2;
            *(float2*)&g_ctx[row0 + v] = make_float2(cacc[nt][0] * r0, cacc[nt][1] * r0);
            *(float2*)&g_ctx[row1 + v] = make_float2(cacc[nt][2] * r1, cacc[nt][3] * r1);
        }
    }
}

// ---------------------------------------------------------------------------
// K3: attn *= rinv[row]
// ---------------------------------------------------------------------------
__global__ void norm_attn(float* __restrict__ attn)
{
    size_t i = (size_t)blockIdx.x * blockDim.x + threadIdx.x;
    size_t row = i >> 9;
    float r = __ldg(&g_rinv[row]);
    float4* p = (float4*)attn;
    float4 v = p[i];
    v.x *= r; v.y *= r; v.z *= r; v.w *= r;
    p[i] = v;
}

// ---------------------------------------------------------------------------
// K4: out = LayerNorm(g_ctx @ W_fc + g_R) * gamma + beta
// ---------------------------------------------------------------------------
__global__ __launch_bounds__(256) void out_ln(const float* __restrict__ Wfc,
                                              const float* __restrict__ gamma,
                                              const float* __restrict__ beta,
                                              float* __restrict__ out)
{
    __shared__ float sA[64][36];
    __shared__ float sW[32][132];
    __shared__ float red1[64][17];
    __shared__ float red2[64][17];
    __shared__ float smu[64];
    __shared__ float srs[64];

    const int tid = threadIdx.x;
    const int tx = tid & 15, ty = tid >> 4;
    const int r0 = blockIdx.x * 64;

    float acc[4][8];
#pragma unroll
    for (int r = 0; r < 4; r++)
#pragma unroll
        for (int c = 0; c < 8; c++) acc[r][c] = 0.f;

    for (int kk = 0; kk < DM; kk += 32) {
        for (int t = tid; t < 64 * 32; t += 256) {
            int r = t >> 5, i = t & 31;
            sA[r][i] = g_ctx[(size_t)(r0 + r) * DM + kk + i];
        }
        for (int t = tid; t < 32 * 128; t += 256) {
            int i = t >> 7, c = t & 127;
            sW[i][c] = Wfc[(size_t)(kk + i) * DM + c];
        }
        __syncthreads();
#pragma unroll
        for (int i = 0; i < 32; i++) {
            float a[4];
#pragma unroll
            for (int r = 0; r < 4; r++) a[r] = sA[ty * 4 + r][i];
            float4 w0 = *(const float4*)&sW[i][tx * 8];
            float4 w1 = *(const float4*)&sW[i][tx * 8 + 4];
            float wv[8] = {w0.x, w0.y, w0.z, w0.w, w1.x, w1.y, w1.z, w1.w};
#pragma unroll
            for (int r = 0; r < 4; r++)
#pragma unroll
                for (int c = 0; c < 8; c++) acc[r][c] += a[r] * wv[c];
        }
        __syncthreads();
    }

#pragma unroll
    for (int r = 0; r < 4; r++) {
        size_t row = (size_t)(r0 + ty * 4 + r);
        float4 rv0 = *(const float4*)&g_R[row * DM + tx * 8];
        float4 rv1 = *(const float4*)&g_R[row * DM + tx * 8 + 4];
        float rsv[8] = {rv0.x, rv0.y, rv0.z, rv0.w, rv1.x, rv1.y, rv1.z, rv1.w};
        float ps = 0.f, pq = 0.f;
#pragma unroll
        for (int c = 0; c < 8; c++) {
            acc[r][c] += rsv[c];
            ps += acc[r][c];
            pq += acc[r][c] * acc[r][c];
        }
        red1[ty * 4 + r][tx] = ps;
        red2[ty * 4 + r][tx] = pq;
    }
    __syncthreads();
    if (tid < 64) {
        float s = 0.f, q = 0.f;
#pragma unroll
        for (int j = 0; j < 16; j++) { s += red1[tid][j]; q += red2[tid][j]; }
        float mu = s * (1.0f / 128.0f);
        float var = q * (1.0f / 128.0f) - mu * mu;
        smu[tid] = mu;
        srs[tid] = rsqrtf(var + 1e-5f);
    }
    __syncthreads();

    float4 g0 = *(const float4*)&gamma[tx * 8];
    float4 g1 = *(const float4*)&gamma[tx * 8 + 4];
    float4 b0 = *(const float4*)&beta[tx * 8];
    float4 b1 = *(const float4*)&beta[tx * 8 + 4];
    float gs[8] = {g0.x, g0.y, g0.z, g0.w, g1.x, g1.y, g1.z, g1.w};
    float bs[8] = {b0.x, b0.y, b0.z, b0.w, b1.x, b1.y, b1.z, b1.w};

#pragma unroll
    for (int r = 0; r < 4; r++) {
        float mu = smu[ty * 4 + r];
        float rstd = srs[ty * 4 + r];
        size_t row = (size_t)(r0 + ty * 4 + r);
        float o[8];
#pragma unroll
        for (int c = 0; c < 8; c++) o[c] = (acc[r][c] - mu) * rstd * gs[c] + bs[c];
        *(float4*)&out[row * DM + tx * 8]     = make_float4(o[0], o[1], o[2], o[3]);
        *(float4*)&out[row * DM + tx * 8 + 4] = make_float4(o[4], o[5], o[6], o[7]);
    }
}

// ---------------------------------------------------------------------------
extern "C" void kernel_launch(void* const* d_in, const int* in_sizes, int n_in,
                              void* d_out, int out_size)
{
    const float* inQ  = (const float*)d_in[0];
    const float* inK  = (const float*)d_in[1];
    const float* inV  = (const float*)d_in[2];
    const unsigned char* mask = (const unsigned char*)d_in[3];
    const float* Wfc0 = (const float*)d_in[4];
    const float* WQ   = (const float*)d_in[5];
    const float* WK   = (const float*)d_in[6];
    const float* WV   = (const float*)d_in[7];
    const float* Wfc  = (const float*)d_in[8];
    const float* gam  = (const float*)d_in[9];
    const float* bet  = (const float*)d_in[10];
    float* out  = (float*)d_out;
    float* attn = out + OUT_ELEMS;

    detect_mask<<<1, 256>>>(mask);
    zero_rinv<<<BATCH * 4 * SEQ / 256, 256>>>();   // filler: keeps ncu window

    gemm_proj4<<<dim3(NR / 64, 4), 256>>>(inQ, inK, inV, Wfc0, WQ, WK, WV);

    cudaFuncSetAttribute(attn_mma, cudaFuncAttributeMaxDynamicSharedMemorySize,
                         (int)SMEM_BYTES);
    dim3 agrid(SEQ / TQ, BATCH * 4);
    attn_mma<<<agrid, 256, SMEM_BYTES>>>(mask, attn);

    size_t nf4 = (size_t)BATCH * 4 * SEQ * SEQ / 4;
    norm_attn<<<(unsigned)(nf4 / 256), 256>>>(attn);

    out_ln<<<NR / 64, 256>>>(Wfc, gam, bet, out);
}